// round 13
// baseline (speedup 1.0000x reference)
#include <cuda_runtime.h>
#include <cuda_bf16.h>
#include <mma.h>
#include <math.h>
#include <stdint.h>

using namespace nvcuda;

// Problem constants (SPINN1: B=128, T=40, D_HID=512, D_TRK=256)
#define BB   128
#define TT   40
#define DD   512
#define TRK  256
#define CAP  (TT + 2)            // 42
#define TWOD (2 * DD)            // 1024
#define KTRK (3 * DD + TRK)      // 1792  (xT = [buf_h | s1_h | s2_h | th])
#define NTRK (4 * TRK)           // 1024
#define KXR  (2 * DD)            // 1024  (xR = [s2_h | s1_h])
#define NRED (5 * DD)            // 2560
// 6-term bf16 split: sections A=[h1|h1|h2|h1|h3|h2], W=[w1|w2|w1|w3|w1|w2]
#define K6T  (6 * KTRK)          // 10752
#define K6R  (6 * KXR)           // 6144
#define K6S  (6 * TRK)           // 1536
#define SPLIT_T 6                // tracker: 8n x 6sp tiles, 56 slabs (of 32) each
#define SPLIT_R 4                // reduce:  20n x 4sp tiles, 48 slabs each
#define SPLIT_S 4                // strk:    20n x 4sp tiles, 12 slabs, ACC into partR 0..3
#define NT_TRK (8 * SPLIT_T)     // 48
#define NT_A   (NT_TRK + 20 * SPLIT_R)  // 128 (one wave)
#define LDS_PAD 40               // smem row stride (bf16 elems), BK=32 + 8 pad

// ---------------- device state (no runtime allocation allowed) --------------
__device__ __align__(16) float g_stack[BB * CAP * TWOD];
__device__ __align__(16) float g_tc[BB * TRK];
__device__ int   g_sptr[BB];
__device__ int   g_blen[BB];
__device__ __align__(16) __nv_bfloat16 g_xT6[BB * K6T];
__device__ __align__(16) __nv_bfloat16 g_xR6[BB * K6R];
__device__ __align__(16) __nv_bfloat16 g_th6[BB * K6S];
__device__ __align__(16) float g_partT[SPLIT_T * BB * NTRK];
__device__ __align__(16) float g_partR[SPLIT_R * BB * NRED];
__device__ int   g_trans[BB];
__device__ __align__(16) __nv_bfloat16 g_Wt6[NTRK * K6T];   // 22 MB
__device__ __align__(16) __nv_bfloat16 g_Wr6[NRED * K6R];   // 31.5 MB
__device__ __align__(16) __nv_bfloat16 g_Ws6[NRED * K6S];   // 7.9 MB
__device__ __align__(16) float g_btrk[NTRK];                // b_ih + b_hh

__device__ __forceinline__ float sigf(float x) { return 1.0f / (1.0f + expf(-x)); }

__device__ __forceinline__ void split3(float x, __nv_bfloat16& a, __nv_bfloat16& b,
                                       __nv_bfloat16& c) {
    a = __float2bfloat16(x);
    float r = x - __bfloat162float(a);
    b = __float2bfloat16(r);
    r -= __bfloat162float(b);
    c = __float2bfloat16(r);
}

// write x into the 6 A-side sections (h1 at s=0,1,3; h2 at s=2,5; h3 at s=4)
__device__ __forceinline__ void put6A(__nv_bfloat16* base, int K, int off, float x) {
    __nv_bfloat16 h1, h2, h3;
    split3(x, h1, h2, h3);
    base[0 * K + off] = h1; base[1 * K + off] = h1; base[3 * K + off] = h1;
    base[2 * K + off] = h2; base[5 * K + off] = h2;
    base[4 * K + off] = h3;
}
// write w into the 6 W-side sections (w1 at s=0,2,4; w2 at s=1,5; w3 at s=3)
__device__ __forceinline__ void put6W(__nv_bfloat16* base, int K, int off, float w) {
    __nv_bfloat16 w1, w2, w3;
    split3(w, w1, w2, w3);
    base[0 * K + off] = w1; base[2 * K + off] = w1; base[4 * K + off] = w1;
    base[1 * K + off] = w2; base[5 * K + off] = w2;
    base[3 * K + off] = w3;
}

// ---------------- init: split weights into 6-section bf16, init state -------
__global__ void k_init(const float* __restrict__ buffers,
                       const float* __restrict__ W_ih, const float* __restrict__ W_hh,
                       const float* __restrict__ b_ih, const float* __restrict__ b_hh,
                       const float* __restrict__ W_left, const float* __restrict__ W_right,
                       const float* __restrict__ W_track) {
    int stride = gridDim.x * blockDim.x;
    int tid0 = blockIdx.x * blockDim.x + threadIdx.x;

    for (int idx = tid0; idx < NTRK * KTRK; idx += stride) {
        int n = idx / KTRK, k = idx - n * KTRK;
        float w = (k < 3 * DD) ? W_ih[n * (3 * DD) + k] : W_hh[n * TRK + (k - 3 * DD)];
        put6W(g_Wt6 + (size_t)n * K6T, KTRK, k, w);
    }
    for (int idx = tid0; idx < NRED * KXR; idx += stride) {
        int n = idx / KXR, k = idx - n * KXR;
        float w = (k < DD) ? W_left[n * DD + k] : W_right[n * DD + (k - DD)];
        put6W(g_Wr6 + (size_t)n * K6R, KXR, k, w);
    }
    for (int idx = tid0; idx < NRED * TRK; idx += stride) {
        int n = idx / TRK, k = idx - n * TRK;
        put6W(g_Ws6 + (size_t)n * K6S, TRK, k, W_track[n * TRK + k]);
    }
    for (int idx = tid0; idx < NTRK; idx += stride) g_btrk[idx] = b_ih[idx] + b_hh[idx];
    for (int idx = tid0; idx < BB * TWOD; idx += stride) {
        int b = idx / TWOD, j = idx - b * TWOD;
        float v = buffers[(long)b * TT * TWOD + j];   // buffers[b, 0, j]
        g_stack[((long)b * CAP + 0) * TWOD + j] = v;
        g_stack[((long)b * CAP + 1) * TWOD + j] = v;
    }
    for (int idx = tid0; idx < BB * TRK; idx += stride) {
        int b = idx / TRK, j = idx - b * TRK;
        g_tc[idx] = 0.f;
        put6A(g_th6 + (size_t)b * K6S, TRK, j, 0.f);
    }
    for (int idx = tid0; idx < BB; idx += stride) { g_sptr[idx] = 2; g_blen[idx] = TT; }
}

// ---------------- gather + split inputs for step 0 --------------------------
__global__ void k_prep(const float* __restrict__ buffers) {
    int b = blockIdx.x, j = threadIdx.x;   // 768 threads
    int sptr = g_sptr[b], blen = g_blen[b];
    const float* bt = buffers + ((long)b * TT + (blen - 1)) * TWOD;
    const float* s1 = g_stack + ((long)b * CAP + (sptr - 1)) * TWOD;
    const float* s2 = g_stack + ((long)b * CAP + (sptr - 2)) * TWOD;
    __nv_bfloat16* xT = g_xT6 + (size_t)b * K6T;
    __nv_bfloat16* xR = g_xR6 + (size_t)b * K6R;
    if (j < DD) {
        put6A(xT, KTRK, j, bt[j]);
        put6A(xT, KTRK, DD + j, s1[j]);
        put6A(xT, KTRK, 2 * DD + j, s2[j]);
        put6A(xR, KXR, j, s2[j]);
        put6A(xR, KXR, DD + j, s1[j]);
    } else if (j < DD + TRK) {
        put6A(xT, KTRK, 3 * DD + (j - DD), 0.f);
    }
}

// ---------------- wmma GEMM tile: Cp[128, nBase..+128) (=|+=) A6*W6^T -------
// 256 threads (8 warps, 2x4 of 64x32 tiles). BK=32 bf16, dbl-buffered smem,
// register prefetch, HMMA bf16 -> fp32 accum.
template <bool ACC>
__device__ __forceinline__ void gemm_tile(const __nv_bfloat16* __restrict__ A, int ldA,
                                          const __nv_bfloat16* __restrict__ W, int ldW,
                                          float* __restrict__ Cp, int N,
                                          int nBase, int kBase, int slabs) {
    __shared__ __align__(32) __nv_bfloat16 As[2][128 * LDS_PAD];
    __shared__ __align__(32) __nv_bfloat16 Ws[2][128 * LDS_PAD];
    int tid = threadIdx.x;
    int wid = tid >> 5;
    int wm = wid & 1;        // 2 m-tiles of 64
    int wn = wid >> 1;       // 4 n-tiles of 32
    int row = tid >> 1;                // loader: 2 threads per row
    int co  = (tid & 1) * 16;          // 16 bf16 = 32B per thread piece

    wmma::fragment<wmma::accumulator, 16, 16, 16, float> acc[4][2];
    #pragma unroll
    for (int i = 0; i < 4; i++)
        #pragma unroll
        for (int j = 0; j < 2; j++) {
            if (ACC) {
                float* p = Cp + (long)(wm * 64 + i * 16) * N + nBase + wn * 32 + j * 16;
                wmma::load_matrix_sync(acc[i][j], p, N, wmma::mem_row_major);
            } else {
                wmma::fill_fragment(acc[i][j], 0.0f);
            }
        }

    uint4 pa0, pa1, pw0, pw1;
    auto gload = [&](int it) {
        const uint4* ap = (const uint4*)(A + (long)row * ldA + kBase + it * 32 + co);
        pa0 = ap[0]; pa1 = ap[1];
        const uint4* wp = (const uint4*)(W + (long)(nBase + row) * ldW + kBase + it * 32 + co);
        pw0 = wp[0]; pw1 = wp[1];
    };
    auto sstore = [&](int buf) {
        uint4* d = (uint4*)&As[buf][row * LDS_PAD + co];
        d[0] = pa0; d[1] = pa1;
        uint4* e = (uint4*)&Ws[buf][row * LDS_PAD + co];
        e[0] = pw0; e[1] = pw1;
    };

    gload(0);
    sstore(0);
    __syncthreads();

    for (int it = 0; it < slabs; it++) {
        int buf = it & 1;
        bool more = (it + 1) < slabs;
        if (more) gload(it + 1);
        #pragma unroll
        for (int kk = 0; kk < 32; kk += 16) {
            wmma::fragment<wmma::matrix_a, 16, 16, 16, __nv_bfloat16, wmma::row_major> af[4];
            wmma::fragment<wmma::matrix_b, 16, 16, 16, __nv_bfloat16, wmma::col_major> bf[2];
            #pragma unroll
            for (int i = 0; i < 4; i++)
                wmma::load_matrix_sync(af[i], &As[buf][(wm * 64 + i * 16) * LDS_PAD + kk], LDS_PAD);
            #pragma unroll
            for (int j = 0; j < 2; j++)
                wmma::load_matrix_sync(bf[j], &Ws[buf][(wn * 32 + j * 16) * LDS_PAD + kk], LDS_PAD);
            #pragma unroll
            for (int i = 0; i < 4; i++)
                #pragma unroll
                for (int j = 0; j < 2; j++)
                    wmma::mma_sync(acc[i][j], af[i], bf[j], acc[i][j]);
        }
        if (more) {
            __syncthreads();
            sstore(buf ^ 1);
            __syncthreads();
        }
    }

    #pragma unroll
    for (int i = 0; i < 4; i++)
        #pragma unroll
        for (int j = 0; j < 2; j++) {
            float* p = Cp + (long)(wm * 64 + i * 16) * N + nBase + wn * 32 + j * 16;
            wmma::store_matrix_sync(p, acc[i][j], N, wmma::mem_row_major);
        }
}

// ---------------- phase A: tracker + reduce GEMMs (128 blocks, one wave) ----
__global__ __launch_bounds__(256) void k_gemmA() {
    int t = blockIdx.x;
    if (t < NT_TRK) {              // tracker: 8n x 6sp, 56 slabs, K'=10752
        int nt = t & 7, sp = t >> 3;
        gemm_tile<false>(g_xT6, K6T, g_Wt6, K6T,
                         g_partT + (size_t)sp * BB * NTRK, NTRK,
                         nt * 128, sp * 56 * 32, 56);
    } else {                       // reduce: 20n x 4sp, 48 slabs, K'=6144
        int tt = t - NT_TRK;
        int nt = tt % 20, sp = tt / 20;
        gemm_tile<false>(g_xR6, K6R, g_Wr6, K6R,
                         g_partR + (size_t)sp * BB * NRED, NRED,
                         nt * 128, sp * 48 * 32, 48);
    }
}

// ---------------- phase C: W_track @ th, ACC into partR slots 0..3 ----------
__global__ __launch_bounds__(256) void k_gemmS() {
    int t = blockIdx.x;            // 80 blocks: 20n x 4sp, 12 slabs, K'=1536
    int nt = t % 20, sp = t / 20;
    gemm_tile<true>(g_th6, K6S, g_Ws6, K6S,
                    g_partR + (size_t)sp * BB * NRED, NRED,
                    nt * 128, sp * 12 * 32, 12);
}

// ---------------- tracker LSTM cell + logits + argmax (512 threads) --------
__global__ __launch_bounds__(512) void k_cell(const float* __restrict__ W_trans,
                                              const float* __restrict__ b_trans,
                                              float* __restrict__ out, int step) {
    int b = blockIdx.x, tid = threadIdx.x;
    __shared__ __align__(16) float part[2][NTRK];
    __shared__ float sp4[4][8];
    {   // slot-split partial sum: half threads take slots 0-2(+bias), half 3-5
        int g = (tid & 255) * 4;
        int h = tid >> 8;
        float4 s;
        if (h == 0) {
            s = *(const float4*)&g_btrk[g];
            #pragma unroll
            for (int sp = 0; sp < 3; sp++) {
                float4 v = *(const float4*)&g_partT[((size_t)sp * BB + b) * NTRK + g];
                s.x += v.x; s.y += v.y; s.z += v.z; s.w += v.w;
            }
        } else {
            s = make_float4(0.f, 0.f, 0.f, 0.f);
            #pragma unroll
            for (int sp = 3; sp < SPLIT_T; sp++) {
                float4 v = *(const float4*)&g_partT[((size_t)sp * BB + b) * NTRK + g];
                s.x += v.x; s.y += v.y; s.z += v.z; s.w += v.w;
            }
        }
        *(float4*)&part[h][g] = s;
    }
    __syncthreads();

    if (tid < 256) {
        int j = tid;
        float gi = part[0][j] + part[1][j];
        float gf = part[0][TRK + j] + part[1][TRK + j];
        float gg = part[0][2 * TRK + j] + part[1][2 * TRK + j];
        float go = part[0][3 * TRK + j] + part[1][3 * TRK + j];
        float tc = g_tc[b * TRK + j];
        float tcn = sigf(gf) * tc + sigf(gi) * tanhf(gg);
        float thn = sigf(go) * tanhf(tcn);
        g_tc[b * TRK + j] = tcn;

        put6A(g_th6 + (size_t)b * K6S, TRK, j, thn);
        put6A(g_xT6 + (size_t)b * K6T, KTRK, 3 * DD + j, thn);

        float p0 = thn * W_trans[0 * TRK + j];
        float p1 = thn * W_trans[1 * TRK + j];
        float p2 = thn * W_trans[2 * TRK + j];
        float p3 = thn * W_trans[3 * TRK + j];
        #pragma unroll
        for (int off = 16; off > 0; off >>= 1) {
            p0 += __shfl_down_sync(0xffffffffu, p0, off);
            p1 += __shfl_down_sync(0xffffffffu, p1, off);
            p2 += __shfl_down_sync(0xffffffffu, p2, off);
            p3 += __shfl_down_sync(0xffffffffu, p3, off);
        }
        if ((j & 31) == 0) {
            int w = j >> 5;
            sp4[0][w] = p0; sp4[1][w] = p1; sp4[2][w] = p2; sp4[3][w] = p3;
        }
    }
    __syncthreads();
    if (tid == 0) {
        float l[4];
        #pragma unroll
        for (int t = 0; t < 4; t++) {
            float s = b_trans[t];
            #pragma unroll
            for (int w = 0; w < 8; w++) s += sp4[t][w];
            l[t] = s;
        }
        float* o = out + ((long)step * BB + b) * 4;
        o[0] = l[0]; o[1] = l[1]; o[2] = l[2]; o[3] = l[3];
        int best = 0; float bv = l[0];                     // jnp.argmax: first max
        if (l[1] > bv) { bv = l[1]; best = 1; }
        if (l[2] > bv) { bv = l[2]; best = 2; }
        if (l[3] > bv) { bv = l[3]; best = 3; }
        g_trans[b] = best;
    }
}

// ---------------- TreeLSTM epilogue + stack update + gather+split ----------
// 640 threads: float4 sums of 4 partR slots, node, then 6-section gather.
__global__ __launch_bounds__(640) void k_epi(const float* __restrict__ buffers,
                                             const float* __restrict__ b_left) {
    __shared__ __align__(16) float lin[NRED];
    int b = blockIdx.x, tid = threadIdx.x;
    {
        int c4 = tid * 4;                    // covers all 2560 columns
        float4 s = *(const float4*)&b_left[c4];
        #pragma unroll
        for (int sp = 0; sp < SPLIT_R; sp++) {
            float4 v = *(const float4*)&g_partR[((size_t)sp * BB + b) * NRED + c4];
            s.x += v.x; s.y += v.y; s.z += v.z; s.w += v.w;
        }
        *(float4*)&lin[c4] = s;
    }
    __syncthreads();

    int sptr = g_sptr[b], blen = g_blen[b];
    int tr = g_trans[b];
    bool do_shift = (tr == 3) && (blen > 2);
    bool do_red   = (tr == 2) && (sptr > 3);
    float* st = g_stack + (long)b * CAP * TWOD;
    const float* bt = buffers + ((long)b * TT + (blen - 1)) * TWOD;

    if (tid < DD) {
        int dd = tid;
        float a  = lin[dd];
        float i_ = lin[DD + dd];
        float f1 = lin[2 * DD + dd];
        float f2 = lin[3 * DD + dd];
        float o_ = lin[4 * DD + dd];
        float s2c = st[(sptr - 2) * TWOD + DD + dd];
        float s1c = st[(sptr - 1) * TWOD + DD + dd];
        float c = tanhf(a) * sigf(i_) + sigf(f1) * s2c + sigf(f2) * s1c;
        float h = sigf(o_) * tanhf(c);
        if (do_red) {
            st[(sptr - 2) * TWOD + dd]      = h;
            st[(sptr - 2) * TWOD + DD + dd] = c;
        }
        if (do_shift) {
            st[sptr * TWOD + dd]      = bt[dd];
            st[sptr * TWOD + DD + dd] = bt[DD + dd];
        }
    }
    int nsp = sptr + (do_shift ? 1 : 0) - (do_red ? 1 : 0);
    int nbl = blen - (do_shift ? 1 : 0);
    if (tid == 0) { g_sptr[b] = nsp; g_blen[b] = nbl; }
    __syncthreads();

    // gather + 6-section split for next step (th handled by k_cell)
    const float* nbt = buffers + ((long)b * TT + (nbl - 1)) * TWOD;
    const float* s1 = st + (nsp - 1) * TWOD;
    const float* s2 = st + (nsp - 2) * TWOD;
    __nv_bfloat16* xT = g_xT6 + (size_t)b * K6T;
    __nv_bfloat16* xR = g_xR6 + (size_t)b * K6R;
    if (tid < DD) {
        int j = tid;
        float v1 = s1[j], v2 = s2[j];
        put6A(xT, KTRK, j, nbt[j]);
        put6A(xT, KTRK, DD + j, v1);
        put6A(xT, KTRK, 2 * DD + j, v2);
        put6A(xR, KXR, j, v2);
        put6A(xR, KXR, DD + j, v1);
    }
}

// ---------------------------------------------------------------------------
extern "C" void kernel_launch(void* const* d_in, const int* in_sizes, int n_in,
                              void* d_out, int out_size) {
    const float* buffers = (const float*)d_in[0];
    const float* W_left  = (const float*)d_in[1];
    const float* b_left  = (const float*)d_in[2];
    const float* W_right = (const float*)d_in[3];
    const float* W_track = (const float*)d_in[4];
    const float* W_ih    = (const float*)d_in[5];
    const float* W_hh    = (const float*)d_in[6];
    const float* b_ih    = (const float*)d_in[7];
    const float* b_hh    = (const float*)d_in[8];
    const float* W_trans = (const float*)d_in[9];
    const float* b_trans = (const float*)d_in[10];
    int n_steps = in_sizes[11] / BB;       // transitions: [n_steps, B]
    float* out = (float*)d_out;

    k_init<<<1184, 256>>>(buffers, W_ih, W_hh, b_ih, b_hh, W_left, W_right, W_track);
    k_prep<<<BB, 768>>>(buffers);

    for (int s = 0; s < n_steps; s++) {
        bool more = (s + 1 < n_steps);
        k_gemmA<<<more ? NT_A : NT_TRK, 256>>>();
        k_cell<<<BB, 512>>>(W_trans, b_trans, out, s);
        if (more) {
            k_gemmS<<<80, 256>>>();
            k_epi<<<BB, 640>>>(buffers, b_left);
        }
    }
}

// round 14
// speedup vs baseline: 2.5875x; 2.5875x over previous
#include <cuda_runtime.h>
#include <math.h>

// Problem constants (SPINN1: B=128, T=40, D_HID=512, D_TRK=256)
#define BB   128
#define TT   40
#define DD   512
#define TRK  256
#define CAP  (TT + 2)            // 42
#define TWOD (2 * DD)            // 1024
#define KTRK (3 * DD + TRK)      // 1792  (xT = [buf_h | s1_h | s2_h | th])
#define NTRK (4 * TRK)           // 1024
#define KRED (2 * DD + TRK)      // 1280  (xRc row = [s2_h | s1_h | th_new])
#define NRED (5 * DD)            // 2560
#define SPLIT_T 17               // tracker split-K: 8n x 17sp = 136 blocks (one wave)
#define SPLIT_RED 7              // reduce split-K: 20n x 7sp x (2 m-strips) blocks
#define MAXSTEPS 64

// ---------------- device state (no runtime allocation allowed) --------------
__device__ __align__(16) float g_stack[BB * CAP * TWOD];
__device__ __align__(16) float g_tc[BB * TRK];
__device__ int   g_sptr[BB];
__device__ int   g_blen[BB];
__device__ __align__(16) float g_xT[BB * KTRK];
__device__ __align__(16) float g_xRc[BB * KRED];          // COMPACTED reduce rows
__device__ __align__(16) float g_partT[SPLIT_T * BB * NTRK];     // 8.9 MB
__device__ __align__(16) float g_partRc[SPLIT_RED * BB * NRED];  // 9.2 MB
__device__ int   g_trans[BB];
__device__ int   g_redidx[BB];                            // compact index or -1
__device__ unsigned g_redcnt[MAXSTEPS];                   // per-step reduce count
__device__ __align__(16) float g_Wtrk[NTRK * KTRK];  // [W_ih | W_hh] concat along K
__device__ __align__(16) float g_Wred[NRED * KRED];  // [W_left | W_right | W_track]
__device__ __align__(16) float g_btrk[NTRK];         // b_ih + b_hh

__device__ __forceinline__ float sigf(float x) { return 1.0f / (1.0f + expf(-x)); }

typedef unsigned long long ull;
__device__ __forceinline__ ull packf2(float x, float y) {
    ull v; asm("mov.b64 %0, {%1,%2};" : "=l"(v) : "f"(x), "f"(y)); return v;
}
__device__ __forceinline__ float2 unpackf2(ull v) {
    float2 r; asm("mov.b64 {%0,%1}, %2;" : "=f"(r.x), "=f"(r.y) : "l"(v)); return r;
}
__device__ __forceinline__ void ffma2(ull& d, ull a, ull b) {
    asm("fma.rn.f32x2 %0, %1, %2, %0;" : "+l"(d) : "l"(a), "l"(b));
}

// ---------------- init: concat weights, init stack/state --------------------
__global__ void k_init(const float* __restrict__ buffers,
                       const float* __restrict__ W_ih, const float* __restrict__ W_hh,
                       const float* __restrict__ b_ih, const float* __restrict__ b_hh,
                       const float* __restrict__ W_left, const float* __restrict__ W_right,
                       const float* __restrict__ W_track) {
    int stride = gridDim.x * blockDim.x;
    int tid0 = blockIdx.x * blockDim.x + threadIdx.x;

    for (int idx = tid0; idx < NTRK * KTRK; idx += stride) {
        int n = idx / KTRK, k = idx - n * KTRK;
        g_Wtrk[idx] = (k < 3 * DD) ? W_ih[n * (3 * DD) + k] : W_hh[n * TRK + (k - 3 * DD)];
    }
    for (int idx = tid0; idx < NRED * KRED; idx += stride) {
        int n = idx / KRED, k = idx - n * KRED;
        float v;
        if (k < DD)            v = W_left[n * DD + k];
        else if (k < 2 * DD)   v = W_right[n * DD + (k - DD)];
        else                   v = W_track[n * TRK + (k - 2 * DD)];
        g_Wred[idx] = v;
    }
    for (int idx = tid0; idx < NTRK; idx += stride) g_btrk[idx] = b_ih[idx] + b_hh[idx];
    for (int idx = tid0; idx < BB * TWOD; idx += stride) {
        int b = idx / TWOD, j = idx - b * TWOD;
        float v = buffers[(long)b * TT * TWOD + j];   // buffers[b, 0, j]
        g_stack[((long)b * CAP + 0) * TWOD + j] = v;
        g_stack[((long)b * CAP + 1) * TWOD + j] = v;
    }
    for (int idx = tid0; idx < BB * TRK; idx += stride) g_tc[idx] = 0.f;
    for (int idx = tid0; idx < BB; idx += stride) {
        g_sptr[idx] = 2; g_blen[idx] = TT; g_redidx[idx] = -1;
    }
    for (int idx = tid0; idx < MAXSTEPS; idx += stride) g_redcnt[idx] = 0u;
}

// ---------------- gather tracker input for step 0 ---------------------------
__global__ void k_prep(const float* __restrict__ buffers) {
    int b = blockIdx.x, tid = threadIdx.x;
    int sptr = g_sptr[b], blen = g_blen[b];
    const float* bt = buffers + ((long)b * TT + (blen - 1)) * TWOD;
    const float* s1 = g_stack + ((long)b * CAP + (sptr - 1)) * TWOD;
    const float* s2 = g_stack + ((long)b * CAP + (sptr - 2)) * TWOD;
    float* xT = g_xT + b * KTRK;
    for (int j = tid; j < DD; j += blockDim.x) {
        xT[j] = bt[j]; xT[DD + j] = s1[j]; xT[2 * DD + j] = s2[j];
    }
    for (int j = tid; j < TRK; j += blockDim.x) xT[3 * DD + j] = 0.f;
}

// ---------------- BM=128 GEMM tile (256 thr, 8x8 microtile, fp32x2) ---------
__device__ __forceinline__ void gemm_tile(const float* __restrict__ A, int lda,
                                          const float* __restrict__ W, int ldw,
                                          float* __restrict__ Cp, int N,
                                          int nBase, int kBase, int iters) {
    __shared__ __align__(16) float As[2][16][128];
    __shared__ __align__(16) float Ws[2][16][128];
    int tid = threadIdx.x;
    int tm = (tid & 15) * 8;
    int tn = (tid >> 4) * 8;
    int lrow0 = tid >> 2;
    int lrow1 = lrow0 + 64;
    int lk    = (tid & 3) * 4;

    ull acc[32];
    #pragma unroll
    for (int i = 0; i < 32; i++) acc[i] = 0ull;

    {   // preload slab 0
        float4 a0 = *(const float4*)(A + (long)lrow0 * lda + kBase + lk);
        float4 a1 = *(const float4*)(A + (long)lrow1 * lda + kBase + lk);
        float4 w0 = *(const float4*)(W + (long)(nBase + lrow0) * ldw + kBase + lk);
        float4 w1 = *(const float4*)(W + (long)(nBase + lrow1) * ldw + kBase + lk);
        As[0][lk + 0][lrow0] = a0.x; As[0][lk + 1][lrow0] = a0.y;
        As[0][lk + 2][lrow0] = a0.z; As[0][lk + 3][lrow0] = a0.w;
        As[0][lk + 0][lrow1] = a1.x; As[0][lk + 1][lrow1] = a1.y;
        As[0][lk + 2][lrow1] = a1.z; As[0][lk + 3][lrow1] = a1.w;
        Ws[0][lk + 0][lrow0] = w0.x; Ws[0][lk + 1][lrow0] = w0.y;
        Ws[0][lk + 2][lrow0] = w0.z; Ws[0][lk + 3][lrow0] = w0.w;
        Ws[0][lk + 0][lrow1] = w1.x; Ws[0][lk + 1][lrow1] = w1.y;
        Ws[0][lk + 2][lrow1] = w1.z; Ws[0][lk + 3][lrow1] = w1.w;
    }
    __syncthreads();

    for (int it = 0; it < iters; it++) {
        int buf = it & 1;
        float4 pa0, pa1, pw0, pw1;
        bool more = (it + 1) < iters;
        if (more) {
            int k0 = kBase + (it + 1) * 16;
            pa0 = *(const float4*)(A + (long)lrow0 * lda + k0 + lk);
            pa1 = *(const float4*)(A + (long)lrow1 * lda + k0 + lk);
            pw0 = *(const float4*)(W + (long)(nBase + lrow0) * ldw + k0 + lk);
            pw1 = *(const float4*)(W + (long)(nBase + lrow1) * ldw + k0 + lk);
        }
        #pragma unroll
        for (int kk = 0; kk < 16; kk++) {
            float4 a0 = *(const float4*)&As[buf][kk][tm];
            float4 a1 = *(const float4*)&As[buf][kk][tm + 4];
            ulonglong2 wlo = *(const ulonglong2*)&Ws[buf][kk][tn];
            ulonglong2 whi = *(const ulonglong2*)&Ws[buf][kk][tn + 4];
            float am[8] = {a0.x, a0.y, a0.z, a0.w, a1.x, a1.y, a1.z, a1.w};
            #pragma unroll
            for (int i = 0; i < 8; i++) {
                ull ad = packf2(am[i], am[i]);
                ffma2(acc[i * 4 + 0], ad, wlo.x);
                ffma2(acc[i * 4 + 1], ad, wlo.y);
                ffma2(acc[i * 4 + 2], ad, whi.x);
                ffma2(acc[i * 4 + 3], ad, whi.y);
            }
        }
        if (more) {
            int nb = buf ^ 1;
            As[nb][lk + 0][lrow0] = pa0.x; As[nb][lk + 1][lrow0] = pa0.y;
            As[nb][lk + 2][lrow0] = pa0.z; As[nb][lk + 3][lrow0] = pa0.w;
            As[nb][lk + 0][lrow1] = pa1.x; As[nb][lk + 1][lrow1] = pa1.y;
            As[nb][lk + 2][lrow1] = pa1.z; As[nb][lk + 3][lrow1] = pa1.w;
            Ws[nb][lk + 0][lrow0] = pw0.x; Ws[nb][lk + 1][lrow0] = pw0.y;
            Ws[nb][lk + 2][lrow0] = pw0.z; Ws[nb][lk + 3][lrow0] = pw0.w;
            Ws[nb][lk + 0][lrow1] = pw1.x; Ws[nb][lk + 1][lrow1] = pw1.y;
            Ws[nb][lk + 2][lrow1] = pw1.z; Ws[nb][lk + 3][lrow1] = pw1.w;
            __syncthreads();
        }
    }

    #pragma unroll
    for (int i = 0; i < 8; i++) {
        float2 v0 = unpackf2(acc[i * 4 + 0]);
        float2 v1 = unpackf2(acc[i * 4 + 1]);
        float2 v2 = unpackf2(acc[i * 4 + 2]);
        float2 v3 = unpackf2(acc[i * 4 + 3]);
        float* row = Cp + (long)(tm + i) * N + nBase + tn;
        *(float4*)(row)     = make_float4(v0.x, v0.y, v1.x, v1.y);
        *(float4*)(row + 4) = make_float4(v2.x, v2.y, v3.x, v3.y);
    }
}

// ---------------- BM=64 GEMM tile (128 thr, 8x8 microtile, fp32x2) ----------
__device__ __forceinline__ void gemm64(const float* __restrict__ A, int lda,
                                       const float* __restrict__ W, int ldw,
                                       float* __restrict__ Cp, int N,
                                       int mBase, int nBase, int kBase, int iters) {
    __shared__ __align__(16) float As[2][16][64];
    __shared__ __align__(16) float Ws[2][16][128];
    int tid = threadIdx.x;           // 128 threads
    int tm = (tid & 7) * 8;          // 8 m-groups
    int tn = (tid >> 3) * 8;         // 16 n-groups
    int arow = tid >> 2;             // A loader: rows 0..31 (+32 with r)
    int wrow = tid >> 2;             // W loader base
    int lk   = (tid & 3) * 4;

    ull acc[32];
    #pragma unroll
    for (int i = 0; i < 32; i++) acc[i] = 0ull;

    auto ldg_store = [&](int buf, int k0) {
        #pragma unroll
        for (int r = 0; r < 2; r++) {      // A: 64 rows x 4 kgroups = 256 tasks
            int row = arow + r * 32;
            float4 v = *(const float4*)(A + (long)(mBase + row) * lda + k0 + lk);
            As[buf][lk + 0][row] = v.x; As[buf][lk + 1][row] = v.y;
            As[buf][lk + 2][row] = v.z; As[buf][lk + 3][row] = v.w;
        }
        #pragma unroll
        for (int r = 0; r < 4; r++) {      // W: 128 rows x 4 kgroups = 512 tasks
            int row = wrow + r * 32;
            float4 v = *(const float4*)(W + (long)(nBase + row) * ldw + k0 + lk);
            Ws[buf][lk + 0][row] = v.x; Ws[buf][lk + 1][row] = v.y;
            Ws[buf][lk + 2][row] = v.z; Ws[buf][lk + 3][row] = v.w;
        }
    };

    ldg_store(0, kBase);
    __syncthreads();

    for (int it = 0; it < iters; it++) {
        int buf = it & 1;
        bool more = (it + 1) < iters;
        #pragma unroll
        for (int kk = 0; kk < 16; kk++) {
            float4 a0 = *(const float4*)&As[buf][kk][tm];
            float4 a1 = *(const float4*)&As[buf][kk][tm + 4];
            ulonglong2 wlo = *(const ulonglong2*)&Ws[buf][kk][tn];
            ulonglong2 whi = *(const ulonglong2*)&Ws[buf][kk][tn + 4];
            float am[8] = {a0.x, a0.y, a0.z, a0.w, a1.x, a1.y, a1.z, a1.w};
            #pragma unroll
            for (int i = 0; i < 8; i++) {
                ull ad = packf2(am[i], am[i]);
                ffma2(acc[i * 4 + 0], ad, wlo.x);
                ffma2(acc[i * 4 + 1], ad, wlo.y);
                ffma2(acc[i * 4 + 2], ad, whi.x);
                ffma2(acc[i * 4 + 3], ad, whi.y);
            }
        }
        if (more) {
            __syncthreads();
            ldg_store(buf ^ 1, kBase + (it + 1) * 16);
            __syncthreads();
        }
    }

    #pragma unroll
    for (int i = 0; i < 8; i++) {
        float2 v0 = unpackf2(acc[i * 4 + 0]);
        float2 v1 = unpackf2(acc[i * 4 + 1]);
        float2 v2 = unpackf2(acc[i * 4 + 2]);
        float2 v3 = unpackf2(acc[i * 4 + 3]);
        float* row = Cp + (long)(mBase + tm + i) * N + nBase + tn;
        *(float4*)(row)     = make_float4(v0.x, v0.y, v1.x, v1.y);
        *(float4*)(row + 4) = make_float4(v2.x, v2.y, v3.x, v3.y);
    }
}

// ---------------- tracker GEMM: grid (8, 17) ---------------------------------
__global__ __launch_bounds__(256) void k_gemmT() {
    int nt = blockIdx.x, sp = blockIdx.y;
    int kS = (sp * 112) / SPLIT_T, kE = ((sp + 1) * 112) / SPLIT_T;
    gemm_tile(g_xT, KTRK, g_Wtrk, KTRK,
              g_partT + (size_t)sp * BB * NTRK, NTRK,
              nt * 128, kS * 16, kE - kS);
}

// ---------------- compacted reduce GEMM: grid (20, 7, 2) --------------------
// Only rows < g_redcnt[step] are live; m-strips past count exit immediately.
__global__ __launch_bounds__(128) void k_gemmRED(int step) {
    int count = (int)g_redcnt[step];
    int mBase = blockIdx.z * 64;
    if (mBase >= count) return;
    int nt = blockIdx.x, sp = blockIdx.y;
    int kS = (sp * 80) / SPLIT_RED, kE = ((sp + 1) * 80) / SPLIT_RED;
    gemm64(g_xRc, KRED, g_Wred, KRED,
           g_partRc + (size_t)sp * BB * NRED, NRED,
           mBase, nt * 128, kS * 16, kE - kS);
}

// ---------------- cell: LSTM + logits + argmax + compact xRc build ----------
__global__ __launch_bounds__(512) void k_cell(const float* __restrict__ W_trans,
                                              const float* __restrict__ b_trans,
                                              float* __restrict__ out, int step) {
    int b = blockIdx.x, tid = threadIdx.x;   // 512 threads
    __shared__ __align__(16) float part[2][NTRK];
    __shared__ float sp4[4][8];
    __shared__ int s_i;
    {   // slot-split partial sum: half threads take slots 0-8(+bias), half 9-16
        int g = (tid & 255) * 4;
        int h = tid >> 8;
        float4 s;
        if (h == 0) {
            s = *(const float4*)&g_btrk[g];
            #pragma unroll
            for (int sp = 0; sp < 9; sp++) {
                float4 v = *(const float4*)&g_partT[((size_t)sp * BB + b) * NTRK + g];
                s.x += v.x; s.y += v.y; s.z += v.z; s.w += v.w;
            }
        } else {
            s = make_float4(0.f, 0.f, 0.f, 0.f);
            #pragma unroll
            for (int sp = 9; sp < SPLIT_T; sp++) {
                float4 v = *(const float4*)&g_partT[((size_t)sp * BB + b) * NTRK + g];
                s.x += v.x; s.y += v.y; s.z += v.z; s.w += v.w;
            }
        }
        *(float4*)&part[h][g] = s;
    }
    __syncthreads();

    int sptr = g_sptr[b];
    float thn = 0.f;
    if (tid < 256) {
        int j = tid;
        float gi = part[0][j] + part[1][j];
        float gf = part[0][TRK + j] + part[1][TRK + j];
        float gg = part[0][2 * TRK + j] + part[1][2 * TRK + j];
        float go = part[0][3 * TRK + j] + part[1][3 * TRK + j];
        float tc = g_tc[b * TRK + j];
        float tcn = sigf(gf) * tc + sigf(gi) * tanhf(gg);
        thn = sigf(go) * tanhf(tcn);
        g_tc[b * TRK + j] = tcn;
        g_xT[b * KTRK + 3 * DD + j] = thn;     // th section for next tracker GEMM

        float p0 = thn * W_trans[0 * TRK + j];
        float p1 = thn * W_trans[1 * TRK + j];
        float p2 = thn * W_trans[2 * TRK + j];
        float p3 = thn * W_trans[3 * TRK + j];
        #pragma unroll
        for (int off = 16; off > 0; off >>= 1) {
            p0 += __shfl_down_sync(0xffffffffu, p0, off);
            p1 += __shfl_down_sync(0xffffffffu, p1, off);
            p2 += __shfl_down_sync(0xffffffffu, p2, off);
            p3 += __shfl_down_sync(0xffffffffu, p3, off);
        }
        if ((tid & 31) == 0) {
            int w = tid >> 5;
            sp4[0][w] = p0; sp4[1][w] = p1; sp4[2][w] = p2; sp4[3][w] = p3;
        }
    }
    __syncthreads();
    if (tid == 0) {
        float l[4];
        #pragma unroll
        for (int t = 0; t < 4; t++) {
            float s = b_trans[t];
            #pragma unroll
            for (int w = 0; w < 8; w++) s += sp4[t][w];
            l[t] = s;
        }
        float* o = out + ((long)step * BB + b) * 4;
        o[0] = l[0]; o[1] = l[1]; o[2] = l[2]; o[3] = l[3];
        int best = 0; float bv = l[0];                     // jnp.argmax: first max
        if (l[1] > bv) { bv = l[1]; best = 1; }
        if (l[2] > bv) { bv = l[2]; best = 2; }
        if (l[3] > bv) { bv = l[3]; best = 3; }
        g_trans[b] = best;
        int i = -1;
        if (best == 2 && sptr > 3) i = (int)atomicAdd(&g_redcnt[step], 1u);
        g_redidx[b] = i;
        s_i = i;
    }
    __syncthreads();
    int i = s_i;
    if (i >= 0) {   // build compacted reduce-GEMM input row [s2_h | s1_h | th]
        const float* st = g_stack + (long)b * CAP * TWOD;
        float* xr = g_xRc + (size_t)i * KRED;
        xr[tid]       = st[(sptr - 2) * TWOD + tid];
        xr[DD + tid]  = st[(sptr - 1) * TWOD + tid];
        if (tid < TRK) xr[2 * DD + tid] = thn;
    }
}

// ---------------- epi: node (reduced rows only) + stack + gather ------------
__global__ __launch_bounds__(640) void k_epi(const float* __restrict__ buffers,
                                             const float* __restrict__ b_left) {
    __shared__ __align__(16) float lin[NRED];
    int b = blockIdx.x, tid = threadIdx.x;   // 640 threads
    int sptr = g_sptr[b], blen = g_blen[b];
    int tr = g_trans[b];
    bool do_shift = (tr == 3) && (blen > 2);
    bool do_red   = (tr == 2) && (sptr > 3);
    int ridx = g_redidx[b];

    if (do_red) {
        int c4 = tid * 4;                    // covers all 2560 columns
        float4 s = *(const float4*)&b_left[c4];
        #pragma unroll
        for (int sp = 0; sp < SPLIT_RED; sp++) {
            float4 v = *(const float4*)&g_partRc[((size_t)sp * BB + ridx) * NRED + c4];
            s.x += v.x; s.y += v.y; s.z += v.z; s.w += v.w;
        }
        *(float4*)&lin[c4] = s;
    }
    __syncthreads();

    float* st = g_stack + (long)b * CAP * TWOD;
    const float* bt = buffers + ((long)b * TT + (blen - 1)) * TWOD;

    if (do_red && tid < DD) {
        int dd = tid;
        float a  = lin[dd];
        float i_ = lin[DD + dd];
        float f1 = lin[2 * DD + dd];
        float f2 = lin[3 * DD + dd];
        float o_ = lin[4 * DD + dd];
        float s2c = st[(sptr - 2) * TWOD + DD + dd];
        float s1c = st[(sptr - 1) * TWOD + DD + dd];
        float c = tanhf(a) * sigf(i_) + sigf(f1) * s2c + sigf(f2) * s1c;
        float h = sigf(o_) * tanhf(c);
        st[(sptr - 2) * TWOD + dd]      = h;
        st[(sptr - 2) * TWOD + DD + dd] = c;
    }
    if (do_shift && tid < DD) {
        st[sptr * TWOD + tid]      = bt[tid];
        st[sptr * TWOD + DD + tid] = bt[DD + tid];
    }
    int nsp = sptr + (do_shift ? 1 : 0) - (do_red ? 1 : 0);
    int nbl = blen - (do_shift ? 1 : 0);
    if (tid == 0) { g_sptr[b] = nsp; g_blen[b] = nbl; }
    __syncthreads();

    // gather tracker input for next step — only rows that changed
    if ((do_red || do_shift) && tid < DD) {
        const float* nbt = buffers + ((long)b * TT + (nbl - 1)) * TWOD;
        const float* s1 = st + (nsp - 1) * TWOD;
        const float* s2 = st + (nsp - 2) * TWOD;
        float* xT = g_xT + b * KTRK;
        int j = tid;
        xT[j] = nbt[j]; xT[DD + j] = s1[j]; xT[2 * DD + j] = s2[j];
    }
}

// ---------------------------------------------------------------------------
extern "C" void kernel_launch(void* const* d_in, const int* in_sizes, int n_in,
                              void* d_out, int out_size) {
    const float* buffers = (const float*)d_in[0];
    const float* W_left  = (const float*)d_in[1];
    const float* b_left  = (const float*)d_in[2];
    const float* W_right = (const float*)d_in[3];
    const float* W_track = (const float*)d_in[4];
    const float* W_ih    = (const float*)d_in[5];
    const float* W_hh    = (const float*)d_in[6];
    const float* b_ih    = (const float*)d_in[7];
    const float* b_hh    = (const float*)d_in[8];
    const float* W_trans = (const float*)d_in[9];
    const float* b_trans = (const float*)d_in[10];
    int n_steps = in_sizes[11] / BB;       // transitions: [n_steps, B]
    float* out = (float*)d_out;

    k_init<<<592, 256>>>(buffers, W_ih, W_hh, b_ih, b_hh, W_left, W_right, W_track);
    k_prep<<<BB, 256>>>(buffers);

    for (int s = 0; s < n_steps; s++) {
        bool more = (s + 1 < n_steps);
        k_gemmT<<<dim3(8, SPLIT_T), 256>>>();
        k_cell<<<BB, 512>>>(W_trans, b_trans, out, s);
        if (more) {
            k_gemmRED<<<dim3(20, SPLIT_RED, 2), 128>>>(s);
            k_epi<<<BB, 640>>>(buffers, b_left);
        }
    }
}

// round 15
// speedup vs baseline: 3.2485x; 1.2555x over previous
#include <cuda_runtime.h>
#include <math.h>

// Problem constants (SPINN1: B=128, T=40, D_HID=512, D_TRK=256)
#define BB   128
#define TT   40
#define DD   512
#define TRK  256
#define CAP  (TT + 2)            // 42
#define TWOD (2 * DD)            // 1024
#define KIH  (3 * DD)            // 1536  (xIc = [buf_h | s1_h | s2_h])
#define NTRK (4 * TRK)           // 1024
#define KRED (2 * DD + TRK)      // 1280  (xRc row = [s2_h | s1_h | th_new])
#define NRED (5 * DD)            // 2560
#define SPI  12                  // W_ih compact GEMM split-K (8 slabs each)
#define SPH  4                   // W_hh GEMM split-K (4 slabs each)
#define SPLIT_RED 10             // reduce split-K (8 slabs each)
#define NB_I (8 * SPI * 2)       // 192 IH blocks (2 m-strips, early-exit)
#define NB_H (8 * SPH * 2)       // 64 HH blocks
#define NB_G (NB_I + NB_H)       // 256
#define MAXSTEPS 64

// ---------------- device state (no runtime allocation allowed) --------------
__device__ __align__(16) float g_stack[BB * CAP * TWOD];
__device__ __align__(16) float g_th[BB * TRK];
__device__ __align__(16) float g_tc[BB * TRK];
__device__ int   g_sptr[BB];
__device__ int   g_blen[BB];
__device__ __align__(16) float g_xIc[BB * KIH];           // COMPACTED changed rows
__device__ __align__(16) float g_xRc[BB * KRED];          // COMPACTED reduce rows
__device__ __align__(16) float g_gih[BB * NTRK];          // cached W_ih . x per row
__device__ __align__(16) float g_partI[SPI * BB * NTRK];
__device__ __align__(16) float g_partH[SPH * BB * NTRK];
__device__ __align__(16) float g_partRc[SPLIT_RED * BB * NRED];
__device__ int   g_trans[BB];
__device__ int   g_redidx[BB];                            // reduce compact idx or -1
__device__ int   g_chgidx[BB];                            // changed compact idx or -1
__device__ unsigned g_redcnt[MAXSTEPS];
__device__ unsigned g_chgcnt[MAXSTEPS + 1];
__device__ __align__(16) float g_Wih[NTRK * KIH];
__device__ __align__(16) float g_Whh[NTRK * TRK];
__device__ __align__(16) float g_Wred[NRED * KRED];  // [W_left | W_right | W_track]
__device__ __align__(16) float g_btrk[NTRK];         // b_ih + b_hh

__device__ __forceinline__ float sigf(float x) { return 1.0f / (1.0f + expf(-x)); }

typedef unsigned long long ull;
__device__ __forceinline__ ull packf2(float x, float y) {
    ull v; asm("mov.b64 %0, {%1,%2};" : "=l"(v) : "f"(x), "f"(y)); return v;
}
__device__ __forceinline__ float2 unpackf2(ull v) {
    float2 r; asm("mov.b64 {%0,%1}, %2;" : "=f"(r.x), "=f"(r.y) : "l"(v)); return r;
}
__device__ __forceinline__ void ffma2(ull& d, ull a, ull b) {
    asm("fma.rn.f32x2 %0, %1, %2, %0;" : "+l"(d) : "l"(a), "l"(b));
}

// ---------------- init -------------------------------------------------------
__global__ void k_init(const float* __restrict__ buffers,
                       const float* __restrict__ W_ih, const float* __restrict__ W_hh,
                       const float* __restrict__ b_ih, const float* __restrict__ b_hh,
                       const float* __restrict__ W_left, const float* __restrict__ W_right,
                       const float* __restrict__ W_track) {
    int stride = gridDim.x * blockDim.x;
    int tid0 = blockIdx.x * blockDim.x + threadIdx.x;

    for (int idx = tid0; idx < NTRK * KIH; idx += stride) g_Wih[idx] = W_ih[idx];
    for (int idx = tid0; idx < NTRK * TRK; idx += stride) g_Whh[idx] = W_hh[idx];
    for (int idx = tid0; idx < NRED * KRED; idx += stride) {
        int n = idx / KRED, k = idx - n * KRED;
        float v;
        if (k < DD)            v = W_left[n * DD + k];
        else if (k < 2 * DD)   v = W_right[n * DD + (k - DD)];
        else                   v = W_track[n * TRK + (k - 2 * DD)];
        g_Wred[idx] = v;
    }
    for (int idx = tid0; idx < NTRK; idx += stride) g_btrk[idx] = b_ih[idx] + b_hh[idx];
    for (int idx = tid0; idx < BB * TWOD; idx += stride) {
        int b = idx / TWOD, j = idx - b * TWOD;
        float v = buffers[(long)b * TT * TWOD + j];   // buffers[b, 0, j]
        g_stack[((long)b * CAP + 0) * TWOD + j] = v;
        g_stack[((long)b * CAP + 1) * TWOD + j] = v;
    }
    for (int idx = tid0; idx < BB * TRK; idx += stride) { g_th[idx] = 0.f; g_tc[idx] = 0.f; }
    for (int idx = tid0; idx < BB; idx += stride) {
        g_sptr[idx] = 2; g_blen[idx] = TT; g_redidx[idx] = -1; g_chgidx[idx] = -1;
    }
    for (int idx = tid0; idx < MAXSTEPS; idx += stride) g_redcnt[idx] = 0u;
    for (int idx = tid0; idx <= MAXSTEPS; idx += stride) g_chgcnt[idx] = 0u;
}

// ---------------- prep: step 0 treats every row as changed ------------------
__global__ void k_prep(const float* __restrict__ buffers) {
    int b = blockIdx.x, tid = threadIdx.x;    // 512 threads
    int sptr = g_sptr[b], blen = g_blen[b];
    const float* bt = buffers + ((long)b * TT + (blen - 1)) * TWOD;
    const float* s1 = g_stack + ((long)b * CAP + (sptr - 1)) * TWOD;
    const float* s2 = g_stack + ((long)b * CAP + (sptr - 2)) * TWOD;
    float* xi = g_xIc + (size_t)b * KIH;      // compact idx = b at step 0
    xi[tid] = bt[tid]; xi[DD + tid] = s1[tid]; xi[2 * DD + tid] = s2[tid];
    if (tid == 0) { g_chgidx[b] = b; g_chgcnt[0] = (unsigned)BB; }
}

// ---------------- BM=64 GEMM tile (128 thr, 8x8 microtile, fp32x2) ----------
__device__ __forceinline__ void gemm64(const float* __restrict__ A, int lda,
                                       const float* __restrict__ W, int ldw,
                                       float* __restrict__ Cp, int N,
                                       int mBase, int nBase, int kBase, int iters) {
    __shared__ __align__(16) float As[2][16][64];
    __shared__ __align__(16) float Ws[2][16][128];
    int tid = threadIdx.x;           // 128 threads
    int tm = (tid & 7) * 8;          // 8 m-groups
    int tn = (tid >> 3) * 8;         // 16 n-groups
    int row4 = tid >> 2;
    int lk   = (tid & 3) * 4;

    ull acc[32];
    #pragma unroll
    for (int i = 0; i < 32; i++) acc[i] = 0ull;

    auto ldg_store = [&](int buf, int k0) {
        #pragma unroll
        for (int r = 0; r < 2; r++) {      // A: 64 rows
            int row = row4 + r * 32;
            float4 v = *(const float4*)(A + (long)(mBase + row) * lda + k0 + lk);
            As[buf][lk + 0][row] = v.x; As[buf][lk + 1][row] = v.y;
            As[buf][lk + 2][row] = v.z; As[buf][lk + 3][row] = v.w;
        }
        #pragma unroll
        for (int r = 0; r < 4; r++) {      // W: 128 rows
            int row = row4 + r * 32;
            float4 v = *(const float4*)(W + (long)(nBase + row) * ldw + k0 + lk);
            Ws[buf][lk + 0][row] = v.x; Ws[buf][lk + 1][row] = v.y;
            Ws[buf][lk + 2][row] = v.z; Ws[buf][lk + 3][row] = v.w;
        }
    };

    ldg_store(0, kBase);
    __syncthreads();

    for (int it = 0; it < iters; it++) {
        int buf = it & 1;
        bool more = (it + 1) < iters;
        #pragma unroll
        for (int kk = 0; kk < 16; kk++) {
            float4 a0 = *(const float4*)&As[buf][kk][tm];
            float4 a1 = *(const float4*)&As[buf][kk][tm + 4];
            ulonglong2 wlo = *(const ulonglong2*)&Ws[buf][kk][tn];
            ulonglong2 whi = *(const ulonglong2*)&Ws[buf][kk][tn + 4];
            float am[8] = {a0.x, a0.y, a0.z, a0.w, a1.x, a1.y, a1.z, a1.w};
            #pragma unroll
            for (int i = 0; i < 8; i++) {
                ull ad = packf2(am[i], am[i]);
                ffma2(acc[i * 4 + 0], ad, wlo.x);
                ffma2(acc[i * 4 + 1], ad, wlo.y);
                ffma2(acc[i * 4 + 2], ad, whi.x);
                ffma2(acc[i * 4 + 3], ad, whi.y);
            }
        }
        if (more) {
            __syncthreads();
            ldg_store(buf ^ 1, kBase + (it + 1) * 16);
            __syncthreads();
        }
    }

    #pragma unroll
    for (int i = 0; i < 8; i++) {
        float2 v0 = unpackf2(acc[i * 4 + 0]);
        float2 v1 = unpackf2(acc[i * 4 + 1]);
        float2 v2 = unpackf2(acc[i * 4 + 2]);
        float2 v3 = unpackf2(acc[i * 4 + 3]);
        float* row = Cp + (long)(mBase + tm + i) * N + nBase + tn;
        *(float4*)(row)     = make_float4(v0.x, v0.y, v1.x, v1.y);
        *(float4*)(row + 4) = make_float4(v2.x, v2.y, v3.x, v3.y);
    }
}

// ---------------- gate GEMMs: W_ih (compact changed) + W_hh (all rows) ------
// 256 blocks x 128 thr. t<192: IH (8n x 12sp x 2 strips, 8 slabs, K=1536,
// early-exit past chgcnt). t>=192: HH (8n x 4sp x 2 strips, 4 slabs, K=256).
__global__ __launch_bounds__(128) void k_gemmG(int step) {
    int t = blockIdx.x;
    if (t < NB_I) {
        int strip = t / 96;
        if (strip * 64 >= (int)g_chgcnt[step]) return;
        int r = t % 96;
        int nt = r & 7, sp = r >> 3;
        gemm64(g_xIc, KIH, g_Wih, KIH,
               g_partI + (size_t)sp * BB * NTRK, NTRK,
               strip * 64, nt * 128, sp * 8 * 16, 8);
    } else {
        int t2 = t - NB_I;
        int strip = t2 / 32;
        int r = t2 % 32;
        int nt = r & 7, sp = r >> 3;
        gemm64(g_th, TRK, g_Whh, TRK,
               g_partH + (size_t)sp * BB * NTRK, NTRK,
               strip * 64, nt * 128, sp * 4 * 16, 4);
    }
}

// ---------------- compacted reduce GEMM: grid (20, 10, 2) -------------------
__global__ __launch_bounds__(128) void k_gemmRED(int step) {
    int count = (int)g_redcnt[step];
    int mBase = blockIdx.z * 64;
    if (mBase >= count) return;
    int nt = blockIdx.x, sp = blockIdx.y;
    gemm64(g_xRc, KRED, g_Wred, KRED,
           g_partRc + (size_t)sp * BB * NRED, NRED,
           mBase, nt * 128, sp * 8 * 16, 8);
}

// ---------------- cell: cached-gih gates + LSTM + argmax + xRc build --------
__global__ __launch_bounds__(512) void k_cell(const float* __restrict__ W_trans,
                                              const float* __restrict__ b_trans,
                                              float* __restrict__ out, int step) {
    int b = blockIdx.x, tid = threadIdx.x;   // 512 threads
    __shared__ __align__(16) float part[2][NTRK];
    __shared__ float sp4[4][8];
    __shared__ int s_i;
    int ci = g_chgidx[b];
    {
        int g = (tid & 255) * 4;
        int h = tid >> 8;
        float4 s;
        if (h == 0) {            // bias + W_hh partials (all rows)
            s = *(const float4*)&g_btrk[g];
            #pragma unroll
            for (int sp = 0; sp < SPH; sp++) {
                float4 v = *(const float4*)&g_partH[((size_t)sp * BB + b) * NTRK + g];
                s.x += v.x; s.y += v.y; s.z += v.z; s.w += v.w;
            }
        } else {                 // W_ih: fresh sum (changed) or cached value
            if (ci >= 0) {
                s = make_float4(0.f, 0.f, 0.f, 0.f);
                #pragma unroll
                for (int sp = 0; sp < SPI; sp++) {
                    float4 v = *(const float4*)&g_partI[((size_t)sp * BB + ci) * NTRK + g];
                    s.x += v.x; s.y += v.y; s.z += v.z; s.w += v.w;
                }
                *(float4*)&g_gih[b * NTRK + g] = s;     // refresh cache
            } else {
                s = *(const float4*)&g_gih[b * NTRK + g];
            }
        }
        *(float4*)&part[h][g] = s;
    }
    __syncthreads();

    int sptr = g_sptr[b];
    float thn = 0.f;
    if (tid < 256) {
        int j = tid;
        float gi = part[0][j] + part[1][j];
        float gf = part[0][TRK + j] + part[1][TRK + j];
        float gg = part[0][2 * TRK + j] + part[1][2 * TRK + j];
        float go = part[0][3 * TRK + j] + part[1][3 * TRK + j];
        float tc = g_tc[b * TRK + j];
        float tcn = sigf(gf) * tc + sigf(gi) * tanhf(gg);
        thn = sigf(go) * tanhf(tcn);
        g_tc[b * TRK + j] = tcn;
        g_th[b * TRK + j] = thn;     // input for next step's W_hh GEMM

        float p0 = thn * W_trans[0 * TRK + j];
        float p1 = thn * W_trans[1 * TRK + j];
        float p2 = thn * W_trans[2 * TRK + j];
        float p3 = thn * W_trans[3 * TRK + j];
        #pragma unroll
        for (int off = 16; off > 0; off >>= 1) {
            p0 += __shfl_down_sync(0xffffffffu, p0, off);
            p1 += __shfl_down_sync(0xffffffffu, p1, off);
            p2 += __shfl_down_sync(0xffffffffu, p2, off);
            p3 += __shfl_down_sync(0xffffffffu, p3, off);
        }
        if ((tid & 31) == 0) {
            int w = tid >> 5;
            sp4[0][w] = p0; sp4[1][w] = p1; sp4[2][w] = p2; sp4[3][w] = p3;
        }
    }
    __syncthreads();
    if (tid == 0) {
        float l[4];
        #pragma unroll
        for (int t = 0; t < 4; t++) {
            float s = b_trans[t];
            #pragma unroll
            for (int w = 0; w < 8; w++) s += sp4[t][w];
            l[t] = s;
        }
        float* o = out + ((long)step * BB + b) * 4;
        o[0] = l[0]; o[1] = l[1]; o[2] = l[2]; o[3] = l[3];
        int best = 0; float bv = l[0];                     // jnp.argmax: first max
        if (l[1] > bv) { bv = l[1]; best = 1; }
        if (l[2] > bv) { bv = l[2]; best = 2; }
        if (l[3] > bv) { bv = l[3]; best = 3; }
        g_trans[b] = best;
        int i = -1;
        if (best == 2 && sptr > 3) i = (int)atomicAdd(&g_redcnt[step], 1u);
        g_redidx[b] = i;
        s_i = i;
    }
    __syncthreads();
    int i = s_i;
    if (i >= 0) {   // build compacted reduce-GEMM row [s2_h | s1_h | th]
        const float* st = g_stack + (long)b * CAP * TWOD;
        float* xr = g_xRc + (size_t)i * KRED;
        xr[tid]       = st[(sptr - 2) * TWOD + tid];
        xr[DD + tid]  = st[(sptr - 1) * TWOD + tid];
        if (tid < TRK) xr[2 * DD + tid] = thn;
    }
}

// ---------------- epi: node + stack update + compact changed-row gather -----
__global__ __launch_bounds__(640) void k_epi(const float* __restrict__ buffers,
                                             const float* __restrict__ b_left, int step) {
    __shared__ __align__(16) float lin[NRED];
    __shared__ int s_ni;
    int b = blockIdx.x, tid = threadIdx.x;   // 640 threads
    int sptr = g_sptr[b], blen = g_blen[b];
    int tr = g_trans[b];
    bool do_shift = (tr == 3) && (blen > 2);
    bool do_red   = (tr == 2) && (sptr > 3);
    int ridx = g_redidx[b];

    if (do_red) {
        int c4 = tid * 4;                    // covers all 2560 columns
        float4 s = *(const float4*)&b_left[c4];
        #pragma unroll
        for (int sp = 0; sp < SPLIT_RED; sp++) {
            float4 v = *(const float4*)&g_partRc[((size_t)sp * BB + ridx) * NRED + c4];
            s.x += v.x; s.y += v.y; s.z += v.z; s.w += v.w;
        }
        *(float4*)&lin[c4] = s;
    }
    __syncthreads();

    float* st = g_stack + (long)b * CAP * TWOD;
    const float* bt = buffers + ((long)b * TT + (blen - 1)) * TWOD;

    if (do_red && tid < DD) {
        int dd = tid;
        float a  = lin[dd];
        float i_ = lin[DD + dd];
        float f1 = lin[2 * DD + dd];
        float f2 = lin[3 * DD + dd];
        float o_ = lin[4 * DD + dd];
        float s2c = st[(sptr - 2) * TWOD + DD + dd];
        float s1c = st[(sptr - 1) * TWOD + DD + dd];
        float c = tanhf(a) * sigf(i_) + sigf(f1) * s2c + sigf(f2) * s1c;
        float h = sigf(o_) * tanhf(c);
        st[(sptr - 2) * TWOD + dd]      = h;
        st[(sptr - 2) * TWOD + DD + dd] = c;
    }
    if (do_shift && tid < DD) {
        st[sptr * TWOD + tid]      = bt[tid];
        st[sptr * TWOD + DD + tid] = bt[DD + tid];
    }
    int nsp = sptr + (do_shift ? 1 : 0) - (do_red ? 1 : 0);
    int nbl = blen - (do_shift ? 1 : 0);
    bool changed = do_shift || do_red;
    if (tid == 0) {
        g_sptr[b] = nsp; g_blen[b] = nbl;
        int ni = -1;
        if (changed) ni = (int)atomicAdd(&g_chgcnt[step + 1], 1u);
        g_chgidx[b] = ni;
        s_ni = ni;
    }
    __syncthreads();

    // compact gather of the changed row's new [buf|s1|s2] for next gemmG
    int ni = s_ni;
    if (ni >= 0 && tid < DD) {
        const float* nbt = buffers + ((long)b * TT + (nbl - 1)) * TWOD;
        const float* s1 = st + (nsp - 1) * TWOD;
        const float* s2 = st + (nsp - 2) * TWOD;
        float* xi = g_xIc + (size_t)ni * KIH;
        xi[tid] = nbt[tid]; xi[DD + tid] = s1[tid]; xi[2 * DD + tid] = s2[tid];
    }
}

// ---------------------------------------------------------------------------
extern "C" void kernel_launch(void* const* d_in, const int* in_sizes, int n_in,
                              void* d_out, int out_size) {
    const float* buffers = (const float*)d_in[0];
    const float* W_left  = (const float*)d_in[1];
    const float* b_left  = (const float*)d_in[2];
    const float* W_right = (const float*)d_in[3];
    const float* W_track = (const float*)d_in[4];
    const float* W_ih    = (const float*)d_in[5];
    const float* W_hh    = (const float*)d_in[6];
    const float* b_ih    = (const float*)d_in[7];
    const float* b_hh    = (const float*)d_in[8];
    const float* W_trans = (const float*)d_in[9];
    const float* b_trans = (const float*)d_in[10];
    int n_steps = in_sizes[11] / BB;       // transitions: [n_steps, B]
    float* out = (float*)d_out;

    k_init<<<592, 256>>>(buffers, W_ih, W_hh, b_ih, b_hh, W_left, W_right, W_track);
    k_prep<<<BB, 512>>>(buffers);

    for (int s = 0; s < n_steps; s++) {
        bool more = (s + 1 < n_steps);
        k_gemmG<<<NB_G, 128>>>(s);
        k_cell<<<BB, 512>>>(W_trans, b_trans, out, s);
        if (more) {
            k_gemmRED<<<dim3(20, SPLIT_RED, 2), 128>>>(s);
            k_epi<<<BB, 640>>>(buffers, b_left, s);
        }
    }
}